// round 15
// baseline (speedup 1.0000x reference)
#include <cuda_runtime.h>
#include <cuda_bf16.h>
#include <cuda_fp16.h>
#include <cstdint>

// Problem constants
#define NROWS   12288
#define DK      128
#define MTILES  96           // NROWS / 128
#define JC      8            // j-tiles per work item (chunk)
#define ITEMS   624          // sum_i ceil((96-i)/8)
#define GRID    296          // 2 CTAs per SM -> exactly one wave (co-resident)
#define NTHREADS 256

// SMEM layout (dynamic): A tile 32KB, B double buffer 2x32KB  (96KB -> 2 CTAs/SM)
#define SM_A     0
#define SM_B0    32768
#define SM_B1    65536
#define SM_TOTAL 98304

// x is pre-scaled by sqrt(log2(e)/T), so MMA acc = sim * EXP_SCALE directly.
static constexpr float EXP_SCALE = 1.4426950408889634f / 0.07f;   // 20.6099...
static constexpr float PRE_SCALE = 4.53981598f;                   // sqrt(EXP_SCALE)
static constexpr float H_BIAS    = 16.0f;      // acc initialized to -16 -> biased exps
static constexpr float H_UNBIAS  = 65536.0f;   // 2^16

// Scratch (allocation-free)
__device__ __nv_bfloat16 g_xbf[NROWS * DK];
__device__ float g_rowsum[NROWS];
__device__ int   g_ticket;
__device__ int   g_sync;      // phase-1 grid barrier (reset by finalizer)
__device__ int   g_done;      // phase-3 completion counter (reset by finalizer)

// ---------------- PTX helpers (base sm_103 target only) ----------------
__device__ __forceinline__ uint32_t smem_u32(const void* p) {
    uint32_t a;
    asm("{ .reg .u64 t; cvta.to.shared.u64 t, %1; cvt.u32.u64 %0, t; }" : "=r"(a) : "l"(p));
    return a;
}

__device__ __forceinline__ void cp16(uint32_t dst, const void* src) {
    asm volatile("cp.async.cg.shared.global [%0], [%1], 16;" :: "r"(dst), "l"(src));
}
#define CP_COMMIT() asm volatile("cp.async.commit_group;" ::: "memory")
#define CP_WAIT1()  asm volatile("cp.async.wait_group 1;" ::: "memory")
#define CP_WAIT0()  asm volatile("cp.async.wait_group 0;" ::: "memory")

__device__ __forceinline__ void ldm4(uint32_t addr, uint32_t* r) {
    asm volatile("ldmatrix.sync.aligned.m8n8.x4.shared.b16 {%0,%1,%2,%3}, [%4];"
        : "=r"(r[0]), "=r"(r[1]), "=r"(r[2]), "=r"(r[3]) : "r"(addr));
}

__device__ __forceinline__ void mma16816(float* c, const uint32_t* a, const uint32_t* b) {
    asm volatile(
        "mma.sync.aligned.m16n8k16.row.col.f32.bf16.bf16.f32 "
        "{%0,%1,%2,%3}, {%4,%5,%6,%7}, {%8,%9}, {%0,%1,%2,%3};"
        : "+f"(c[0]), "+f"(c[1]), "+f"(c[2]), "+f"(c[3])
        : "r"(a[0]), "r"(a[1]), "r"(a[2]), "r"(a[3]), "r"(b[0]), "r"(b[1]));
}

__device__ __forceinline__ float fast_exp2(float x) {
    float r;
    asm("ex2.approx.f32 %0, %1;" : "=f"(r) : "f"(x));
    return r;
}

__device__ __forceinline__ uint32_t pack_f16x2(float hi, float lo) {
    uint32_t r;
    asm("cvt.rn.f16x2.f32 %0, %1, %2;" : "=r"(r) : "f"(hi), "f"(lo));
    return r;
}
__device__ __forceinline__ uint32_t ex2_f16x2(uint32_t v) {
    uint32_t r;
    asm("ex2.approx.f16x2 %0, %1;" : "=r"(r) : "r"(v));
    return r;
}
__device__ __forceinline__ uint32_t hadd2(uint32_t a, uint32_t b) {
    uint32_t r;
    asm("add.rn.f16x2 %0, %1, %2;" : "=r"(r) : "r"(a), "r"(b));
    return r;
}
__device__ __forceinline__ uint32_t prmt(uint32_t a, uint32_t b, uint32_t sel) {
    uint32_t r;
    asm("prmt.b32 %0, %1, %2, %3;" : "=r"(r) : "r"(a), "r"(b), "r"(sel));
    return r;
}
__device__ __forceinline__ float h2_lo(uint32_t v) {
    __half2 h = *reinterpret_cast<__half2*>(&v);
    return __low2float(h);
}
__device__ __forceinline__ float h2_hi(uint32_t v) {
    __half2 h = *reinterpret_cast<__half2*>(&v);
    return __high2float(h);
}

// ---------------- device sub-steps ----------------

// Load one 128x128 bf16 tile (row-major 256B rows) into SMEM with XOR-16B swizzle.
__device__ __forceinline__ void issue_tile_load(uint32_t sdst, const __nv_bfloat16* gsrc,
                                                int tid) {
    const char* base = (const char*)gsrc;
    #pragma unroll
    for (int t = 0; t < 8; t++) {
        int q   = tid + t * NTHREADS;      // 0..2047
        int row = q >> 4;
        int col = q & 15;
        cp16(sdst + row * 256 + ((col ^ (row & 7)) << 4),
             base + row * 256 + col * 16);
    }
}

// MMA for one 128x128 tile into acc; acc pre-initialized to -H_BIAS so the
// result is sim*EXP_SCALE - 16 (biased log2-domain) directly.
__device__ __forceinline__ void tile_mma(uint32_t sA, uint32_t bufb,
                                         float (&acc)[4][4][4],
                                         int wm, int wn, int rsel, int csel) {
    #pragma unroll
    for (int mt = 0; mt < 4; mt++)
        #pragma unroll
        for (int nt = 0; nt < 4; nt++)
            #pragma unroll
            for (int ci = 0; ci < 4; ci++) acc[mt][nt][ci] = -H_BIAS;

    #pragma unroll
    for (int kb = 0; kb < 8; kb++) {
        uint32_t a[4][4];
        #pragma unroll
        for (int mt = 0; mt < 4; mt++) {
            int row = wm * 64 + mt * 16 + rsel;
            uint32_t ad = sA + row * 256 + (((kb * 2 + csel) ^ (row & 7)) << 4);
            ldm4(ad, a[mt]);
        }
        uint32_t bf[4][2];
        #pragma unroll
        for (int np = 0; np < 2; np++) {
            int row = wn * 32 + np * 16 + rsel;
            uint32_t ad = bufb + row * 256 + (((kb * 2 + csel) ^ (row & 7)) << 4);
            uint32_t t4[4];
            ldm4(ad, t4);
            bf[np * 2 + 0][0] = t4[0]; bf[np * 2 + 0][1] = t4[2];
            bf[np * 2 + 1][0] = t4[1]; bf[np * 2 + 1][1] = t4[3];
        }
        #pragma unroll
        for (int mt = 0; mt < 4; mt++)
            #pragma unroll
            for (int nt = 0; nt < 4; nt++)
                mma16816(acc[mt][nt], a[mt], bf[nt]);
    }
}

// Diagonal-tile epilogue: f32 biased exps into rowpart only.
__device__ __forceinline__ void tile_epi_diag(const float (&acc)[4][4][4],
                                              float (&rowpart)[8]) {
    #pragma unroll
    for (int mt = 0; mt < 4; mt++)
        #pragma unroll
        for (int nt = 0; nt < 4; nt++) {
            float e0 = fast_exp2(acc[mt][nt][0]);
            float e1 = fast_exp2(acc[mt][nt][1]);
            float e2 = fast_exp2(acc[mt][nt][2]);
            float e3 = fast_exp2(acc[mt][nt][3]);
            rowpart[mt * 2 + 0] += e0 + e1;
            rowpart[mt * 2 + 1] += e2 + e3;
        }
}

// Off-diagonal epilogue: biased f16x2 exps; rowh[mt]=(lo=row r, hi=row r+8),
// colh[nt]=(lo=even col, hi=odd col).  c0=(r,c) c1=(r,c+1) c2=(r+8,c) c3=(r+8,c+1).
__device__ __forceinline__ void tile_epi_h2(const float (&acc)[4][4][4],
                                            uint32_t (&rowh)[4], uint32_t (&colh)[4]) {
    #pragma unroll
    for (int mt = 0; mt < 4; mt++)
        #pragma unroll
        for (int nt = 0; nt < 4; nt++) {
            uint32_t p01 = ex2_f16x2(pack_f16x2(acc[mt][nt][1], acc[mt][nt][0]));
            uint32_t p23 = ex2_f16x2(pack_f16x2(acc[mt][nt][3], acc[mt][nt][2]));
            colh[nt] = hadd2(colh[nt], hadd2(p01, p23));    // (lo=e0+e2, hi=e1+e3)
            uint32_t t1 = prmt(p01, p23, 0x5410);           // (lo=e0, hi=e2)
            uint32_t t2 = prmt(p01, p23, 0x7632);           // (lo=e1, hi=e3)
            rowh[mt] = hadd2(rowh[mt], hadd2(t1, t2));      // (lo=e0+e1, hi=e2+e3)
        }
}

// Flush f16x2 column partials of one completed off-diag tile (packed reduce).
__device__ __forceinline__ void col_flush_h(uint32_t (&colh)[4], int jglob,
                                            int wn, int lane) {
    #pragma unroll
    for (int nt = 0; nt < 4; nt++) {
        uint32_t v = colh[nt];
        v = hadd2(v, __shfl_xor_sync(0xffffffffu, v, 4));
        v = hadd2(v, __shfl_xor_sync(0xffffffffu, v, 8));
        v = hadd2(v, __shfl_xor_sync(0xffffffffu, v, 16));
        if (lane < 4) {
            int col = jglob * 128 + wn * 32 + nt * 8 + lane * 2;
            atomicAdd(&g_rowsum[col],     H_UNBIAS * h2_lo(v));
            atomicAdd(&g_rowsum[col + 1], H_UNBIAS * h2_hi(v));
        }
        colh[nt] = 0u;
    }
}

// ---------------- the single fused kernel ----------------

__global__ void __launch_bounds__(NTHREADS, 2)
uniform_loss_fused(const float* __restrict__ x, float* __restrict__ out) {
    extern __shared__ char smem[];
    uint32_t sb = smem_u32(smem);
    __shared__ int s_item;
    __shared__ float s_red[8];

    const int tid  = threadIdx.x;
    const int lane = tid & 31;
    const int w    = tid >> 5;      // 0..7
    const int wm   = w & 1;         // 2 M-groups of 64 rows
    const int wn   = w >> 1;        // 4 N-groups of 32 cols
    const int rsel = lane & 15;
    const int csel = lane >> 4;
    const int g    = lane >> 2;

    // ======== Phase 1: convert fp32 -> bf16 (pre-scaled), reset accumulators ====
    {
        const int gt = blockIdx.x * NTHREADS + tid;
        const int NV4 = NROWS * DK / 4;
        __nv_bfloat162* dst = reinterpret_cast<__nv_bfloat162*>(g_xbf);
        #pragma unroll 1
        for (int i = gt; i < NV4; i += GRID * NTHREADS) {
            float4 v = reinterpret_cast<const float4*>(x)[i];
            dst[2 * i]     = __floats2bfloat162_rn(v.x * PRE_SCALE, v.y * PRE_SCALE);
            dst[2 * i + 1] = __floats2bfloat162_rn(v.z * PRE_SCALE, v.w * PRE_SCALE);
        }
        #pragma unroll 1
        for (int i = gt; i < NROWS; i += GRID * NTHREADS) g_rowsum[i] = 0.0f;
        if (gt == 0) g_ticket = GRID;
        __threadfence();
        __syncthreads();
        // Grid barrier (all 296 CTAs are co-resident: one wave at occupancy 2)
        if (tid == 0) {
            atomicAdd(&g_sync, 1);
            while (atomicAdd(&g_sync, 0) < GRID) { __nanosleep(64); }
        }
        __syncthreads();
        __threadfence();
    }

    // ======== Phase 2: persistent symmetric GEMM + exp accumulation ========
    const uint32_t sA = sb + SM_A;
    const uint32_t sBuf[2] = { sb + SM_B0, sb + SM_B1 };

    int it = blockIdx.x;            // first item: static; rest via ticket
    #pragma unroll 1
    while (it < ITEMS) {
        // Decode item -> (i, chunk): row i covers j in [i, 96), chunked by 8.
        int t = it, i = 0;
        #pragma unroll 1
        for (; i < MTILES; i++) {
            int chunks = (MTILES - i + JC - 1) >> 3;
            if (t < chunks) break;
            t -= chunks;
        }
        const int j0 = i + t * JC;
        const int nj = min(JC, MTILES - j0);
        const bool diag0 = (j0 == i);

        // Prologue: A tile + B(j0) as group0; B(j0+1) as group1 (if present)
        issue_tile_load(sA,      g_xbf + (size_t)i  * 128 * DK, tid);
        issue_tile_load(sBuf[0], g_xbf + (size_t)j0 * 128 * DK, tid);
        CP_COMMIT();
        if (nj > 1) {
            issue_tile_load(sBuf[1], g_xbf + (size_t)(j0 + 1) * 128 * DK, tid);
            CP_COMMIT();
        }

        float rowpart[8];
        uint32_t rowh[4], colh[4];
        #pragma unroll
        for (int r = 0; r < 8; r++) rowpart[r] = 0.0f;
        #pragma unroll
        for (int r = 0; r < 4; r++) { rowh[r] = 0u; colh[r] = 0u; }

        float acc[4][4][4];

        #pragma unroll 1
        for (int jj = 0; jj < nj; jj++) {
            if (jj == nj - 1) { CP_WAIT0(); } else { CP_WAIT1(); }
            __syncthreads();
            tile_mma(sA, sBuf[jj & 1], acc, wm, wn, rsel, csel);
            __syncthreads();
            if (jj + 2 < nj) {
                issue_tile_load(sBuf[jj & 1],
                                g_xbf + (size_t)(j0 + jj + 2) * 128 * DK, tid);
                CP_COMMIT();
            }
            // Epilogue overlaps the cp.async just issued.
            if (jj == 0 && diag0) {
                tile_epi_diag(acc, rowpart);
            } else {
                tile_epi_h2(acc, rowh, colh);
                col_flush_h(colh, j0 + jj, wn, lane);
            }
        }

        // Merge biased f16 row partials into f32 rowpart, then flush rows
        // (everything is biased by 2^-16; unbias once here).
        #pragma unroll
        for (int mt = 0; mt < 4; mt++) {
            rowpart[mt * 2 + 0] += h2_lo(rowh[mt]);
            rowpart[mt * 2 + 1] += h2_hi(rowh[mt]);
        }
        #pragma unroll
        for (int r = 0; r < 8; r++) {
            float v = rowpart[r];
            v += __shfl_xor_sync(0xffffffffu, v, 1);
            v += __shfl_xor_sync(0xffffffffu, v, 2);
            if ((lane & 3) == 0) {
                int row = i * 128 + wm * 64 + (r >> 1) * 16 + (r & 1) * 8 + g;
                atomicAdd(&g_rowsum[row], H_UNBIAS * v);
            }
        }

        // Grab next item (dynamic balance).
        __syncthreads();
        if (tid == 0) s_item = atomicAdd(&g_ticket, 1);
        __syncthreads();
        it = s_item;
    }

    // ======== Phase 3: last CTA finalizes ========
    __threadfence();
    __syncthreads();
    if (tid == 0) s_item = atomicAdd(&g_done, 1);
    __syncthreads();
    if (s_item == GRID - 1) {
        __threadfence();
        float L = 0.0f;
        #pragma unroll 1
        for (int r = tid; r < NROWS; r += NTHREADS) L += __logf(g_rowsum[r]);
        #pragma unroll
        for (int o = 16; o > 0; o >>= 1) L += __shfl_xor_sync(0xffffffffu, L, o);
        if (lane == 0) s_red[w] = L;
        __syncthreads();
        if (tid == 0) {
            float tsum = 0.0f;
            #pragma unroll
            for (int k = 0; k < 8; k++) tsum += s_red[k];
            out[0] = tsum * (1.0f / (float)NROWS);
            // Reset counters for the next graph replay.
            g_sync = 0;
            g_done = 0;
        }
    }
}

// ---------------- host launch ----------------

extern "C" void kernel_launch(void* const* d_in, const int* in_sizes, int n_in,
                              void* d_out, int out_size) {
    const float* x = (const float*)d_in[0];
    float* out = (float*)d_out;

    cudaFuncSetAttribute(uniform_loss_fused,
                         cudaFuncAttributeMaxDynamicSharedMemorySize, SM_TOTAL);
    uniform_loss_fused<<<GRID, NTHREADS, SM_TOTAL>>>(x, out);
}

// round 16
// speedup vs baseline: 1.2495x; 1.2495x over previous
#include <cuda_runtime.h>
#include <cuda_bf16.h>
#include <cuda_fp16.h>
#include <cstdint>

// Problem constants
#define NROWS   12288
#define DK      128
#define MTILES  96           // NROWS / 128
#define JC      8            // j-tiles per work item (chunk)
#define ITEMS   624          // sum_i ceil((96-i)/8)
#define GRID    296          // 2 CTAs per SM
#define NTHREADS 256

// SMEM layout: A tile 32KB shared; per-group (2 groups) double-buffered
// 64-row B halves, 16KB each.  Total 96KB -> 2 CTAs/SM.
#define SM_A     0
#define SM_BG    32768       // group g buffer b at SM_BG + g*32768 + b*16384
#define SM_TOTAL 98304

// x is pre-scaled by sqrt(log2(e)/T), so MMA acc = sim * EXP_SCALE directly.
static constexpr float EXP_SCALE = 1.4426950408889634f / 0.07f;   // 20.6099...
static constexpr float PRE_SCALE = 4.53981598f;                   // sqrt(EXP_SCALE)
static constexpr float H_BIAS    = 16.0f;      // acc initialized to -16 -> biased exps
static constexpr float H_UNBIAS  = 65536.0f;   // 2^16

// Scratch (allocation-free)
__device__ __nv_bfloat16 g_xbf[NROWS * DK];
__device__ float g_rowsum[NROWS];
__device__ int   g_ticket;

// ---------------- PTX helpers (base sm_103 target only) ----------------
__device__ __forceinline__ uint32_t smem_u32(const void* p) {
    uint32_t a;
    asm("{ .reg .u64 t; cvta.to.shared.u64 t, %1; cvt.u32.u64 %0, t; }" : "=r"(a) : "l"(p));
    return a;
}

__device__ __forceinline__ void cp16(uint32_t dst, const void* src) {
    asm volatile("cp.async.cg.shared.global [%0], [%1], 16;" :: "r"(dst), "l"(src));
}
#define CP_COMMIT() asm volatile("cp.async.commit_group;" ::: "memory")
#define CP_WAIT1()  asm volatile("cp.async.wait_group 1;" ::: "memory")
#define CP_WAIT0()  asm volatile("cp.async.wait_group 0;" ::: "memory")

// Group barrier: 4 warps (128 threads), barrier id 1+grp (0 = full CTA).
#define BARG(grp) asm volatile("bar.sync %0, 128;" :: "r"((grp) + 1) : "memory")

__device__ __forceinline__ void ldm4(uint32_t addr, uint32_t* r) {
    asm volatile("ldmatrix.sync.aligned.m8n8.x4.shared.b16 {%0,%1,%2,%3}, [%4];"
        : "=r"(r[0]), "=r"(r[1]), "=r"(r[2]), "=r"(r[3]) : "r"(addr));
}

__device__ __forceinline__ void mma16816(float* c, const uint32_t* a, const uint32_t* b) {
    asm volatile(
        "mma.sync.aligned.m16n8k16.row.col.f32.bf16.bf16.f32 "
        "{%0,%1,%2,%3}, {%4,%5,%6,%7}, {%8,%9}, {%0,%1,%2,%3};"
        : "+f"(c[0]), "+f"(c[1]), "+f"(c[2]), "+f"(c[3])
        : "r"(a[0]), "r"(a[1]), "r"(a[2]), "r"(a[3]), "r"(b[0]), "r"(b[1]));
}

__device__ __forceinline__ float fast_exp2(float x) {
    float r;
    asm("ex2.approx.f32 %0, %1;" : "=f"(r) : "f"(x));
    return r;
}

__device__ __forceinline__ uint32_t pack_f16x2(float hi, float lo) {
    uint32_t r;
    asm("cvt.rn.f16x2.f32 %0, %1, %2;" : "=r"(r) : "f"(hi), "f"(lo));
    return r;
}
__device__ __forceinline__ uint32_t ex2_f16x2(uint32_t v) {
    uint32_t r;
    asm("ex2.approx.f16x2 %0, %1;" : "=r"(r) : "r"(v));
    return r;
}
__device__ __forceinline__ uint32_t hadd2(uint32_t a, uint32_t b) {
    uint32_t r;
    asm("add.rn.f16x2 %0, %1, %2;" : "=r"(r) : "r"(a), "r"(b));
    return r;
}
__device__ __forceinline__ uint32_t prmt(uint32_t a, uint32_t b, uint32_t sel) {
    uint32_t r;
    asm("prmt.b32 %0, %1, %2, %3;" : "=r"(r) : "r"(a), "r"(b), "r"(sel));
    return r;
}
__device__ __forceinline__ float h2_lo(uint32_t v) {
    __half2 h = *reinterpret_cast<__half2*>(&v);
    return __low2float(h);
}
__device__ __forceinline__ float h2_hi(uint32_t v) {
    __half2 h = *reinterpret_cast<__half2*>(&v);
    return __high2float(h);
}

// ---------------- kernels ----------------

__global__ void convert_kernel(const float* __restrict__ x, float* __restrict__ out) {
    int i = blockIdx.x * blockDim.x + threadIdx.x;
    if (i < NROWS * DK / 4) {
        float4 v = reinterpret_cast<const float4*>(x)[i];
        __nv_bfloat162* dst = reinterpret_cast<__nv_bfloat162*>(g_xbf);
        dst[2 * i]     = __floats2bfloat162_rn(v.x * PRE_SCALE, v.y * PRE_SCALE);
        dst[2 * i + 1] = __floats2bfloat162_rn(v.z * PRE_SCALE, v.w * PRE_SCALE);
    }
    if (i < NROWS) g_rowsum[i] = 0.0f;   // reset every launch (graph replay)
    if (i == 0) { out[0] = 0.0f; g_ticket = GRID; }
}

// Full 128-row A tile load (256 threads), XOR-16B swizzle, 256B rows.
__device__ __forceinline__ void issue_tile_load(uint32_t sdst, const __nv_bfloat16* gsrc,
                                                int tid) {
    const char* base = (const char*)gsrc;
    #pragma unroll
    for (int t = 0; t < 8; t++) {
        int q   = tid + t * NTHREADS;      // 0..2047
        int row = q >> 4;
        int col = q & 15;
        cp16(sdst + row * 256 + ((col ^ (row & 7)) << 4),
             base + row * 256 + col * 16);
    }
}

// 64-row B half-tile load (128 threads of one group), same swizzle.
__device__ __forceinline__ void issue_half_load(uint32_t sdst, const __nv_bfloat16* gsrc,
                                                int gtid) {
    const char* base = (const char*)gsrc;
    #pragma unroll
    for (int t = 0; t < 8; t++) {
        int q   = gtid + t * 128;          // 0..1023
        int row = q >> 4;                  // 0..63
        int col = q & 15;
        cp16(sdst + row * 256 + ((col ^ (row & 7)) << 4),
             base + row * 256 + col * 16);
    }
}

// MMA for one 128(M)x64(N-half) tile into acc (group-private B buffer).
// acc pre-initialized to -H_BIAS -> result is biased log2-domain.
__device__ __forceinline__ void tile_mma(uint32_t sA, uint32_t bufb,
                                         float (&acc)[4][4][4],
                                         int wm, int wnl, int rsel, int csel) {
    #pragma unroll
    for (int mt = 0; mt < 4; mt++)
        #pragma unroll
        for (int nt = 0; nt < 4; nt++)
            #pragma unroll
            for (int ci = 0; ci < 4; ci++) acc[mt][nt][ci] = -H_BIAS;

    #pragma unroll
    for (int kb = 0; kb < 8; kb++) {
        uint32_t a[4][4];
        #pragma unroll
        for (int mt = 0; mt < 4; mt++) {
            int row = wm * 64 + mt * 16 + rsel;
            uint32_t ad = sA + row * 256 + (((kb * 2 + csel) ^ (row & 7)) << 4);
            ldm4(ad, a[mt]);
        }
        uint32_t bf[4][2];
        #pragma unroll
        for (int np = 0; np < 2; np++) {
            int row = wnl * 32 + np * 16 + rsel;   // 0..63 within the half
            uint32_t ad = bufb + row * 256 + (((kb * 2 + csel) ^ (row & 7)) << 4);
            uint32_t t4[4];
            ldm4(ad, t4);
            bf[np * 2 + 0][0] = t4[0]; bf[np * 2 + 0][1] = t4[2];
            bf[np * 2 + 1][0] = t4[1]; bf[np * 2 + 1][1] = t4[3];
        }
        #pragma unroll
        for (int mt = 0; mt < 4; mt++)
            #pragma unroll
            for (int nt = 0; nt < 4; nt++)
                mma16816(acc[mt][nt], a[mt], bf[nt]);
    }
}

// Diagonal-tile epilogue: f32 biased exps into rowpart only.
__device__ __forceinline__ void tile_epi_diag(const float (&acc)[4][4][4],
                                              float (&rowpart)[8]) {
    #pragma unroll
    for (int mt = 0; mt < 4; mt++)
        #pragma unroll
        for (int nt = 0; nt < 4; nt++) {
            float e0 = fast_exp2(acc[mt][nt][0]);
            float e1 = fast_exp2(acc[mt][nt][1]);
            float e2 = fast_exp2(acc[mt][nt][2]);
            float e3 = fast_exp2(acc[mt][nt][3]);
            rowpart[mt * 2 + 0] += e0 + e1;
            rowpart[mt * 2 + 1] += e2 + e3;
        }
}

// Off-diagonal epilogue: biased f16x2 exps.
__device__ __forceinline__ void tile_epi_h2(const float (&acc)[4][4][4],
                                            uint32_t (&rowh)[4], uint32_t (&colh)[4]) {
    #pragma unroll
    for (int mt = 0; mt < 4; mt++)
        #pragma unroll
        for (int nt = 0; nt < 4; nt++) {
            uint32_t p01 = ex2_f16x2(pack_f16x2(acc[mt][nt][1], acc[mt][nt][0]));
            uint32_t p23 = ex2_f16x2(pack_f16x2(acc[mt][nt][3], acc[mt][nt][2]));
            colh[nt] = hadd2(colh[nt], hadd2(p01, p23));    // (lo=e0+e2, hi=e1+e3)
            uint32_t t1 = prmt(p01, p23, 0x5410);           // (lo=e0, hi=e2)
            uint32_t t2 = prmt(p01, p23, 0x7632);           // (lo=e1, hi=e3)
            rowh[mt] = hadd2(rowh[mt], hadd2(t1, t2));      // (lo=e0+e1, hi=e2+e3)
        }
}

// Flush f16x2 column partials (wn = global column group of this warp, 0..3).
__device__ __forceinline__ void col_flush_h(uint32_t (&colh)[4], int jglob,
                                            int wn, int lane) {
    #pragma unroll
    for (int nt = 0; nt < 4; nt++) {
        uint32_t v = colh[nt];
        v = hadd2(v, __shfl_xor_sync(0xffffffffu, v, 4));
        v = hadd2(v, __shfl_xor_sync(0xffffffffu, v, 8));
        v = hadd2(v, __shfl_xor_sync(0xffffffffu, v, 16));
        if (lane < 4) {
            int col = jglob * 128 + wn * 32 + nt * 8 + lane * 2;
            atomicAdd(&g_rowsum[col],     H_UNBIAS * h2_lo(v));
            atomicAdd(&g_rowsum[col + 1], H_UNBIAS * h2_hi(v));
        }
        colh[nt] = 0u;
    }
}

__global__ void __launch_bounds__(NTHREADS, 2)
uniform_loss_main() {
    extern __shared__ char smem[];
    uint32_t sb = smem_u32(smem);
    __shared__ int s_item;

    const int tid  = threadIdx.x;
    const int lane = tid & 31;
    const int w    = tid >> 5;       // 0..7
    const int wm   = w & 1;          // 2 M-groups of 64 rows
    const int wn   = w >> 1;         // 4 global N-groups of 32 cols
    const int wnl  = wn & 1;         // N-group within the group's 64-col half
    const int grp  = w >> 2;         // 0: cols 0-63, 1: cols 64-127
    const int gtid = tid & 127;      // thread id within group
    const int rsel = lane & 15;
    const int csel = lane >> 4;
    const int g    = lane >> 2;

    const uint32_t sA = sb + SM_A;
    const uint32_t sBuf[2] = { sb + SM_BG + grp * 32768,
                               sb + SM_BG + grp * 32768 + 16384 };

    int it = blockIdx.x;             // first item: static; rest via ticket
    #pragma unroll 1
    while (it < ITEMS) {
        // Decode item -> (i, chunk): row i covers j in [i, 96), chunked by 8.
        int t = it, i = 0;
        #pragma unroll 1
        for (; i < MTILES; i++) {
            int chunks = (MTILES - i + JC - 1) >> 3;
            if (t < chunks) break;
            t -= chunks;
        }
        const int j0 = i + t * JC;
        const int nj = min(JC, MTILES - j0);
        const bool diag0 = (j0 == i);

        // Prologue: A (all 256 threads) + group's half of B(j0) -> commit 0;
        // group's half of B(j0+1) -> commit 1.
        issue_tile_load(sA, g_xbf + (size_t)i * 128 * DK, tid);
        issue_half_load(sBuf[0],
                        g_xbf + ((size_t)j0 * 128 + 64 * grp) * DK, gtid);
        CP_COMMIT();
        if (nj > 1) {
            issue_half_load(sBuf[1],
                            g_xbf + ((size_t)(j0 + 1) * 128 + 64 * grp) * DK, gtid);
            CP_COMMIT();
        }

        float rowpart[8];
        uint32_t rowh[4], colh[4];
        #pragma unroll
        for (int r = 0; r < 8; r++) rowpart[r] = 0.0f;
        #pragma unroll
        for (int r = 0; r < 4; r++) { rowh[r] = 0u; colh[r] = 0u; }

        float acc[4][4][4];

        // Group-private pipeline: only 4-warp barriers inside.
        #pragma unroll 1
        for (int jj = 0; jj < nj; jj++) {
            if (jj == nj - 1) { CP_WAIT0(); } else { CP_WAIT1(); }
            BARG(grp);
            tile_mma(sA, sBuf[jj & 1], acc, wm, wnl, rsel, csel);
            BARG(grp);
            if (jj + 2 < nj) {
                issue_half_load(sBuf[jj & 1],
                                g_xbf + ((size_t)(j0 + jj + 2) * 128 + 64 * grp) * DK,
                                gtid);
                CP_COMMIT();
            }
            // Epilogue overlaps the cp.async just issued.
            if (jj == 0 && diag0) {
                tile_epi_diag(acc, rowpart);
            } else {
                tile_epi_h2(acc, rowh, colh);
                col_flush_h(colh, j0 + jj, wn, lane);
            }
        }

        // Merge biased f16 row partials into f32 rowpart, then flush rows
        // (everything is biased by 2^-16; unbias once here).
        #pragma unroll
        for (int mt = 0; mt < 4; mt++) {
            rowpart[mt * 2 + 0] += h2_lo(rowh[mt]);
            rowpart[mt * 2 + 1] += h2_hi(rowh[mt]);
        }
        #pragma unroll
        for (int r = 0; r < 8; r++) {
            float v = rowpart[r];
            v += __shfl_xor_sync(0xffffffffu, v, 1);
            v += __shfl_xor_sync(0xffffffffu, v, 2);
            if ((lane & 3) == 0) {
                int row = i * 128 + wm * 64 + (r >> 1) * 16 + (r & 1) * 8 + g;
                atomicAdd(&g_rowsum[row], H_UNBIAS * v);
            }
        }

        // Item boundary: full-CTA sync (A reuse + ticket).
        __syncthreads();
        if (tid == 0) s_item = atomicAdd(&g_ticket, 1);
        __syncthreads();
        it = s_item;
    }
}

__global__ void finalize_kernel(float* __restrict__ out) {
    int i = blockIdx.x * blockDim.x + threadIdx.x;   // 0..NROWS-1
    float L = __logf(g_rowsum[i]);

    #pragma unroll
    for (int o = 16; o > 0; o >>= 1) L += __shfl_xor_sync(0xffffffffu, L, o);

    __shared__ float ws[8];
    int lane = threadIdx.x & 31, wid = threadIdx.x >> 5;
    if (lane == 0) ws[wid] = L;
    __syncthreads();
    if (threadIdx.x == 0) {
        float t = 0.0f;
        #pragma unroll
        for (int k = 0; k < 8; k++) t += ws[k];
        atomicAdd(out, t * (1.0f / (float)NROWS));
    }
}

// ---------------- host launch ----------------

extern "C" void kernel_launch(void* const* d_in, const int* in_sizes, int n_in,
                              void* d_out, int out_size) {
    const float* x = (const float*)d_in[0];
    float* out = (float*)d_out;

    int nconv = NROWS * DK / 4;
    convert_kernel<<<(nconv + 255) / 256, 256>>>(x, out);

    cudaFuncSetAttribute(uniform_loss_main,
                         cudaFuncAttributeMaxDynamicSharedMemorySize, SM_TOTAL);
    uniform_loss_main<<<GRID, NTHREADS, SM_TOTAL>>>();

    finalize_kernel<<<NROWS / 256, 256>>>(out);
}

// round 17
// speedup vs baseline: 1.2576x; 1.0064x over previous
#include <cuda_runtime.h>
#include <cuda_bf16.h>
#include <cuda_fp16.h>
#include <cstdint>

// Problem constants
#define NROWS   12288
#define DK      128
#define MTILES  96           // NROWS / 128
#define JC      8            // j-tiles per work item (chunk)
#define ITEMS   624          // sum_i ceil((96-i)/8)
#define GRID    296          // 2 CTAs per SM
#define NTHREADS 256

// SMEM layout: A tile 32KB shared; per-group (4 groups of 2 warps)
// double-buffered 32-row B slices, 8KB each.  Total 96KB -> 2 CTAs/SM.
#define SM_A     0
#define SM_BG    32768       // group g buffer b at SM_BG + g*16384 + b*8192
#define SM_TOTAL 98304

// x is pre-scaled by sqrt(log2(e)/T), so MMA acc = sim * EXP_SCALE directly.
static constexpr float EXP_SCALE = 1.4426950408889634f / 0.07f;   // 20.6099...
static constexpr float PRE_SCALE = 4.53981598f;                   // sqrt(EXP_SCALE)
static constexpr float H_BIAS    = 16.0f;      // acc initialized to -16 -> biased exps
static constexpr float H_UNBIAS  = 65536.0f;   // 2^16

// Scratch (allocation-free)
__device__ __nv_bfloat16 g_xbf[NROWS * DK];
__device__ float g_rowsum[NROWS];
__device__ int   g_ticket;

// ---------------- PTX helpers (base sm_103 target only) ----------------
__device__ __forceinline__ uint32_t smem_u32(const void* p) {
    uint32_t a;
    asm("{ .reg .u64 t; cvta.to.shared.u64 t, %1; cvt.u32.u64 %0, t; }" : "=r"(a) : "l"(p));
    return a;
}

__device__ __forceinline__ void cp16(uint32_t dst, const void* src) {
    asm volatile("cp.async.cg.shared.global [%0], [%1], 16;" :: "r"(dst), "l"(src));
}
#define CP_COMMIT() asm volatile("cp.async.commit_group;" ::: "memory")
#define CP_WAIT1()  asm volatile("cp.async.wait_group 1;" ::: "memory")
#define CP_WAIT0()  asm volatile("cp.async.wait_group 0;" ::: "memory")

// Group barrier: 2 warps (64 threads), barrier id 1+grp (0 = full CTA).
#define BARG(grp) asm volatile("bar.sync %0, 64;" :: "r"((grp) + 1) : "memory")

__device__ __forceinline__ void ldm4(uint32_t addr, uint32_t* r) {
    asm volatile("ldmatrix.sync.aligned.m8n8.x4.shared.b16 {%0,%1,%2,%3}, [%4];"
        : "=r"(r[0]), "=r"(r[1]), "=r"(r[2]), "=r"(r[3]) : "r"(addr));
}

__device__ __forceinline__ void mma16816(float* c, const uint32_t* a, const uint32_t* b) {
    asm volatile(
        "mma.sync.aligned.m16n8k16.row.col.f32.bf16.bf16.f32 "
        "{%0,%1,%2,%3}, {%4,%5,%6,%7}, {%8,%9}, {%0,%1,%2,%3};"
        : "+f"(c[0]), "+f"(c[1]), "+f"(c[2]), "+f"(c[3])
        : "r"(a[0]), "r"(a[1]), "r"(a[2]), "r"(a[3]), "r"(b[0]), "r"(b[1]));
}

__device__ __forceinline__ float fast_exp2(float x) {
    float r;
    asm("ex2.approx.f32 %0, %1;" : "=f"(r) : "f"(x));
    return r;
}

__device__ __forceinline__ uint32_t pack_f16x2(float hi, float lo) {
    uint32_t r;
    asm("cvt.rn.f16x2.f32 %0, %1, %2;" : "=r"(r) : "f"(hi), "f"(lo));
    return r;
}
__device__ __forceinline__ uint32_t ex2_f16x2(uint32_t v) {
    uint32_t r;
    asm("ex2.approx.f16x2 %0, %1;" : "=r"(r) : "r"(v));
    return r;
}
__device__ __forceinline__ uint32_t hadd2(uint32_t a, uint32_t b) {
    uint32_t r;
    asm("add.rn.f16x2 %0, %1, %2;" : "=r"(r) : "r"(a), "r"(b));
    return r;
}
__device__ __forceinline__ uint32_t prmt(uint32_t a, uint32_t b, uint32_t sel) {
    uint32_t r;
    asm("prmt.b32 %0, %1, %2, %3;" : "=r"(r) : "r"(a), "r"(b), "r"(sel));
    return r;
}
__device__ __forceinline__ float h2_lo(uint32_t v) {
    __half2 h = *reinterpret_cast<__half2*>(&v);
    return __low2float(h);
}
__device__ __forceinline__ float h2_hi(uint32_t v) {
    __half2 h = *reinterpret_cast<__half2*>(&v);
    return __high2float(h);
}

// ---------------- kernels ----------------

__global__ void convert_kernel(const float* __restrict__ x, float* __restrict__ out) {
    int i = blockIdx.x * blockDim.x + threadIdx.x;
    if (i < NROWS * DK / 4) {
        float4 v = reinterpret_cast<const float4*>(x)[i];
        __nv_bfloat162* dst = reinterpret_cast<__nv_bfloat162*>(g_xbf);
        dst[2 * i]     = __floats2bfloat162_rn(v.x * PRE_SCALE, v.y * PRE_SCALE);
        dst[2 * i + 1] = __floats2bfloat162_rn(v.z * PRE_SCALE, v.w * PRE_SCALE);
    }
    if (i < NROWS) g_rowsum[i] = 0.0f;   // reset every launch (graph replay)
    if (i == 0) { out[0] = 0.0f; g_ticket = GRID; }
}

// Full 128-row A tile load (256 threads), XOR-16B swizzle, 256B rows.
__device__ __forceinline__ void issue_tile_load(uint32_t sdst, const __nv_bfloat16* gsrc,
                                                int tid) {
    const char* base = (const char*)gsrc;
    #pragma unroll
    for (int t = 0; t < 8; t++) {
        int q   = tid + t * NTHREADS;      // 0..2047
        int row = q >> 4;
        int col = q & 15;
        cp16(sdst + row * 256 + ((col ^ (row & 7)) << 4),
             base + row * 256 + col * 16);
    }
}

// 32-row B slice load (64 threads of one group), same swizzle.
__device__ __forceinline__ void issue_slice_load(uint32_t sdst, const __nv_bfloat16* gsrc,
                                                 int gtid) {
    const char* base = (const char*)gsrc;
    #pragma unroll
    for (int t = 0; t < 8; t++) {
        int q   = gtid + t * 64;           // 0..511
        int row = q >> 4;                  // 0..31
        int col = q & 15;
        cp16(sdst + row * 256 + ((col ^ (row & 7)) << 4),
             base + row * 256 + col * 16);
    }
}

// MMA for one 128(M)x32(N-slice) tile into acc (group-private B buffer).
// acc pre-initialized to -H_BIAS -> result is biased log2-domain.
__device__ __forceinline__ void tile_mma(uint32_t sA, uint32_t bufb,
                                         float (&acc)[4][4][4],
                                         int wm, int rsel, int csel) {
    #pragma unroll
    for (int mt = 0; mt < 4; mt++)
        #pragma unroll
        for (int nt = 0; nt < 4; nt++)
            #pragma unroll
            for (int ci = 0; ci < 4; ci++) acc[mt][nt][ci] = -H_BIAS;

    #pragma unroll
    for (int kb = 0; kb < 8; kb++) {
        uint32_t a[4][4];
        #pragma unroll
        for (int mt = 0; mt < 4; mt++) {
            int row = wm * 64 + mt * 16 + rsel;
            uint32_t ad = sA + row * 256 + (((kb * 2 + csel) ^ (row & 7)) << 4);
            ldm4(ad, a[mt]);
        }
        uint32_t bf[4][2];
        #pragma unroll
        for (int np = 0; np < 2; np++) {
            int row = np * 16 + rsel;      // 0..31 within the slice
            uint32_t ad = bufb + row * 256 + (((kb * 2 + csel) ^ (row & 7)) << 4);
            uint32_t t4[4];
            ldm4(ad, t4);
            bf[np * 2 + 0][0] = t4[0]; bf[np * 2 + 0][1] = t4[2];
            bf[np * 2 + 1][0] = t4[1]; bf[np * 2 + 1][1] = t4[3];
        }
        #pragma unroll
        for (int mt = 0; mt < 4; mt++)
            #pragma unroll
            for (int nt = 0; nt < 4; nt++)
                mma16816(acc[mt][nt], a[mt], bf[nt]);
    }
}

// Diagonal-tile epilogue: f32 biased exps into rowpart only.
__device__ __forceinline__ void tile_epi_diag(const float (&acc)[4][4][4],
                                              float (&rowpart)[8]) {
    #pragma unroll
    for (int mt = 0; mt < 4; mt++)
        #pragma unroll
        for (int nt = 0; nt < 4; nt++) {
            float e0 = fast_exp2(acc[mt][nt][0]);
            float e1 = fast_exp2(acc[mt][nt][1]);
            float e2 = fast_exp2(acc[mt][nt][2]);
            float e3 = fast_exp2(acc[mt][nt][3]);
            rowpart[mt * 2 + 0] += e0 + e1;
            rowpart[mt * 2 + 1] += e2 + e3;
        }
}

// Off-diagonal epilogue: biased f16x2 exps.
__device__ __forceinline__ void tile_epi_h2(const float (&acc)[4][4][4],
                                            uint32_t (&rowh)[4], uint32_t (&colh)[4]) {
    #pragma unroll
    for (int mt = 0; mt < 4; mt++)
        #pragma unroll
        for (int nt = 0; nt < 4; nt++) {
            uint32_t p01 = ex2_f16x2(pack_f16x2(acc[mt][nt][1], acc[mt][nt][0]));
            uint32_t p23 = ex2_f16x2(pack_f16x2(acc[mt][nt][3], acc[mt][nt][2]));
            colh[nt] = hadd2(colh[nt], hadd2(p01, p23));    // (lo=e0+e2, hi=e1+e3)
            uint32_t t1 = prmt(p01, p23, 0x5410);           // (lo=e0, hi=e2)
            uint32_t t2 = prmt(p01, p23, 0x7632);           // (lo=e1, hi=e3)
            rowh[mt] = hadd2(rowh[mt], hadd2(t1, t2));      // (lo=e0+e1, hi=e2+e3)
        }
}

// Flush f16x2 column partials (wn = global column group of this warp, 0..3).
__device__ __forceinline__ void col_flush_h(uint32_t (&colh)[4], int jglob,
                                            int wn, int lane) {
    #pragma unroll
    for (int nt = 0; nt < 4; nt++) {
        uint32_t v = colh[nt];
        v = hadd2(v, __shfl_xor_sync(0xffffffffu, v, 4));
        v = hadd2(v, __shfl_xor_sync(0xffffffffu, v, 8));
        v = hadd2(v, __shfl_xor_sync(0xffffffffu, v, 16));
        if (lane < 4) {
            int col = jglob * 128 + wn * 32 + nt * 8 + lane * 2;
            atomicAdd(&g_rowsum[col],     H_UNBIAS * h2_lo(v));
            atomicAdd(&g_rowsum[col + 1], H_UNBIAS * h2_hi(v));
        }
        colh[nt] = 0u;
    }
}

__global__ void __launch_bounds__(NTHREADS, 2)
uniform_loss_main() {
    extern __shared__ char smem[];
    uint32_t sb = smem_u32(smem);
    __shared__ int s_item;

    const int tid  = threadIdx.x;
    const int lane = tid & 31;
    const int w    = tid >> 5;       // 0..7
    const int wm   = w & 1;          // 2 M-groups of 64 rows
    const int wn   = w >> 1;         // 4 global N-groups of 32 cols == group id
    const int gtid = tid & 63;       // thread id within the 2-warp group
    const int rsel = lane & 15;
    const int csel = lane >> 4;
    const int g    = lane >> 2;

    const uint32_t sA = sb + SM_A;
    const uint32_t sBuf[2] = { sb + SM_BG + wn * 16384,
                               sb + SM_BG + wn * 16384 + 8192 };

    int it = blockIdx.x;             // first item: static; rest via ticket
    #pragma unroll 1
    while (it < ITEMS) {
        // Decode item -> (i, chunk): row i covers j in [i, 96), chunked by 8.
        int t = it, i = 0;
        #pragma unroll 1
        for (; i < MTILES; i++) {
            int chunks = (MTILES - i + JC - 1) >> 3;
            if (t < chunks) break;
            t -= chunks;
        }
        const int j0 = i + t * JC;
        const int nj = min(JC, MTILES - j0);
        const bool diag0 = (j0 == i);

        // Prologue: A (all 256 threads) + group's slice of B(j0) -> commit 0;
        // group's slice of B(j0+1) -> commit 1.
        issue_tile_load(sA, g_xbf + (size_t)i * 128 * DK, tid);
        issue_slice_load(sBuf[0],
                         g_xbf + ((size_t)j0 * 128 + 32 * wn) * DK, gtid);
        CP_COMMIT();
        if (nj > 1) {
            issue_slice_load(sBuf[1],
                             g_xbf + ((size_t)(j0 + 1) * 128 + 32 * wn) * DK, gtid);
            CP_COMMIT();
        }

        float rowpart[8];
        uint32_t rowh[4], colh[4];
        #pragma unroll
        for (int r = 0; r < 8; r++) rowpart[r] = 0.0f;
        #pragma unroll
        for (int r = 0; r < 4; r++) { rowh[r] = 0u; colh[r] = 0u; }

        float acc[4][4][4];

        // Group-private pipeline: only 2-warp barriers inside.
        #pragma unroll 1
        for (int jj = 0; jj < nj; jj++) {
            if (jj == nj - 1) { CP_WAIT0(); } else { CP_WAIT1(); }
            BARG(wn);
            tile_mma(sA, sBuf[jj & 1], acc, wm, rsel, csel);
            BARG(wn);
            if (jj + 2 < nj) {
                issue_slice_load(sBuf[jj & 1],
                                 g_xbf + ((size_t)(j0 + jj + 2) * 128 + 32 * wn) * DK,
                                 gtid);
                CP_COMMIT();
            }
            // Epilogue overlaps the cp.async just issued.
            if (jj == 0 && diag0) {
                tile_epi_diag(acc, rowpart);
            } else {
                tile_epi_h2(acc, rowh, colh);
                col_flush_h(colh, j0 + jj, wn, lane);
            }
        }

        // Merge biased f16 row partials into f32 rowpart, then flush rows
        // (everything is biased by 2^-16; unbias once here).
        #pragma unroll
        for (int mt = 0; mt < 4; mt++) {
            rowpart[mt * 2 + 0] += h2_lo(rowh[mt]);
            rowpart[mt * 2 + 1] += h2_hi(rowh[mt]);
        }
        #pragma unroll
        for (int r = 0; r < 8; r++) {
            float v = rowpart[r];
            v += __shfl_xor_sync(0xffffffffu, v, 1);
            v += __shfl_xor_sync(0xffffffffu, v, 2);
            if ((lane & 3) == 0) {
                int row = i * 128 + wm * 64 + (r >> 1) * 16 + (r & 1) * 8 + g;
                atomicAdd(&g_rowsum[row], H_UNBIAS * v);
            }
        }

        // Item boundary: full-CTA sync (A reuse + ticket).
        __syncthreads();
        if (tid == 0) s_item = atomicAdd(&g_ticket, 1);
        __syncthreads();
        it = s_item;
    }
}

__global__ void finalize_kernel(float* __restrict__ out) {
    int i = blockIdx.x * blockDim.x + threadIdx.x;   // 0..NROWS-1
    float L = __logf(g_rowsum[i]);

    #pragma unroll
    for (int o = 16; o > 0; o >>= 1) L += __shfl_xor_sync(0xffffffffu, L, o);

    __shared__ float ws[8];
    int lane = threadIdx.x & 31, wid = threadIdx.x >> 5;
    if (lane == 0) ws[wid] = L;
    __syncthreads();
    if (threadIdx.x == 0) {
        float t = 0.0f;
        #pragma unroll
        for (int k = 0; k < 8; k++) t += ws[k];
        atomicAdd(out, t * (1.0f / (float)NROWS));
    }
}

// ---------------- host launch ----------------

extern "C" void kernel_launch(void* const* d_in, const int* in_sizes, int n_in,
                              void* d_out, int out_size) {
    const float* x = (const float*)d_in[0];
    float* out = (float*)d_out;

    int nconv = NROWS * DK / 4;
    convert_kernel<<<(nconv + 255) / 256, 256>>>(x, out);

    cudaFuncSetAttribute(uniform_loss_main,
                         cudaFuncAttributeMaxDynamicSharedMemorySize, SM_TOTAL);
    uniform_loss_main<<<GRID, NTHREADS, SM_TOTAL>>>();

    finalize_kernel<<<NROWS / 256, 256>>>(out);
}